// round 5
// baseline (speedup 1.0000x reference)
#include <cuda_runtime.h>
#include <cuda_fp16.h>
#include <cstdint>

// Problem constants
#define BATCH 256
#define LSEQ  128
#define D1    512
#define D2    512

// Tiling
#define BM 128
#define BN 128
#define BK 16              // k elements per stage
#define NKT (D1/BK)        // 32 stages
#define ASTRIDE 24         // halves per A smem row (16 + 8 pad)  -> 3*r mod 8 bijective
#define BSTRIDE 136        // halves per B smem row (128 + 8 pad) -> 17*r mod 8 bijective

__device__ __forceinline__ unsigned sptr(const void* p) {
    unsigned a;
    asm("{ .reg .u64 t; cvta.to.shared.u64 t, %1; cvt.u32.u64 %0, t; }" : "=r"(a) : "l"(p));
    return a;
}
__device__ __forceinline__ void ldmx4(unsigned* r, unsigned a) {
    asm volatile("ldmatrix.sync.aligned.m8n8.x4.shared.b16 {%0,%1,%2,%3}, [%4];"
                 : "=r"(r[0]), "=r"(r[1]), "=r"(r[2]), "=r"(r[3]) : "r"(a));
}
__device__ __forceinline__ void ldmx4t(unsigned* r, unsigned a) {
    asm volatile("ldmatrix.sync.aligned.m8n8.x4.trans.shared.b16 {%0,%1,%2,%3}, [%4];"
                 : "=r"(r[0]), "=r"(r[1]), "=r"(r[2]), "=r"(r[3]) : "r"(a));
}
__device__ __forceinline__ void mma16816(float* c, const unsigned* a, const unsigned* b) {
    asm volatile(
        "mma.sync.aligned.m16n8k16.row.col.f32.f16.f16.f32 "
        "{%0,%1,%2,%3}, {%4,%5,%6,%7}, {%8,%9}, {%0,%1,%2,%3};"
        : "+f"(c[0]), "+f"(c[1]), "+f"(c[2]), "+f"(c[3])
        : "r"(a[0]), "r"(a[1]), "r"(a[2]), "r"(a[3]), "r"(b[0]), "r"(b[1]));
}

__global__ void zero_out_kernel(float* o, int n) {
    int i = blockIdx.x * blockDim.x + threadIdx.x;
    if (i < n) o[i] = 0.0f;
}

// grid: (D2/BN = 4, BATCH = 256), block: 256 threads (8 warps, 4m x 2n warp grid)
__global__ __launch_bounds__(256, 2) void pdot_h_kernel(
    const float* __restrict__ t1,
    const float* __restrict__ t2,
    const int*   __restrict__ pidx,
    const float* __restrict__ W,
    float*       __restrict__ out)
{
    __shared__ __align__(16) __half As[2][BM][ASTRIDE];
    __shared__ __align__(16) __half Bs[2][BK][BSTRIDE];

    const int b  = blockIdx.y;
    const int jc = blockIdx.x * BN;
    const int e  = pidx[b];

    const float* Ag  = t1 + (size_t)b * LSEQ * D1;
    const float* Wg  = W  + (size_t)e * D1 * D2;
    const float* T2g = t2 + (size_t)b * LSEQ * D2;

    const int tid  = threadIdx.x;
    const int lane = tid & 31;
    const int warp = tid >> 5;
    const int gid  = lane >> 2;
    const int tig  = lane & 3;
    const int wm   = warp >> 1;     // 0..3 -> 32-row strip
    const int wn   = warp & 1;      // 0..1 -> 64-col strip

    // ---- loader indexing (one pass covers a full stage) ----
    const int al = tid >> 1;              // A row 0..127
    const int ac = (tid & 1) * 8;         // A col chunk (8 halves)
    const int bk = tid >> 4;              // B k-row 0..15
    const int bc = (tid & 15) * 8;        // B n chunk (8 halves)
    const float* agp = Ag + (size_t)al * D1 + ac;
    const float* bgp = Wg + (size_t)bk * D2 + jc + bc;

    float4 ar[2], br[2];
    auto ldg_stage = [&](int k0) {
        ar[0] = *(const float4*)(agp + k0);
        ar[1] = *(const float4*)(agp + k0 + 4);
        br[0] = *(const float4*)(bgp + (size_t)k0 * D2);
        br[1] = *(const float4*)(bgp + (size_t)k0 * D2 + 4);
    };
    auto sts_stage = [&](int s) {
        __half2 h[4];
        h[0] = __floats2half2_rn(ar[0].x, ar[0].y);
        h[1] = __floats2half2_rn(ar[0].z, ar[0].w);
        h[2] = __floats2half2_rn(ar[1].x, ar[1].y);
        h[3] = __floats2half2_rn(ar[1].z, ar[1].w);
        *(uint4*)&As[s][al][ac] = *(uint4*)h;
        h[0] = __floats2half2_rn(br[0].x, br[0].y);
        h[1] = __floats2half2_rn(br[0].z, br[0].w);
        h[2] = __floats2half2_rn(br[1].x, br[1].y);
        h[3] = __floats2half2_rn(br[1].z, br[1].w);
        *(uint4*)&Bs[s][bk][bc] = *(uint4*)h;
    };

    // ---- per-thread ldmatrix source offsets (element units, within a stage) ----
    // A (non-trans): matrix i from lanes 8i..8i+7; row-block from bit3, k-chunk from bit4
    const int a_row = ((lane >> 3) & 1) * 8 + (lane & 7);
    const int a_kch = (lane >> 4) * 8;
    // B (trans): k-row from bits [3]&[0:2], n-chunk from bit4
    const int b_kr  = ((lane >> 3) & 1) * 8 + (lane & 7);
    const int b_nch = (lane >> 4) * 8;

    float acc[2][8][4];
    #pragma unroll
    for (int mi = 0; mi < 2; ++mi)
        #pragma unroll
        for (int ni = 0; ni < 8; ++ni)
            #pragma unroll
            for (int r = 0; r < 4; ++r) acc[mi][ni][r] = 0.0f;

    // ---- prologue ----
    ldg_stage(0);
    sts_stage(0);
    ldg_stage(BK);
    __syncthreads();

    for (int kt = 0; kt < NKT; ++kt) {
        const int s = kt & 1;

        unsigned af[2][4];
        #pragma unroll
        for (int mi = 0; mi < 2; ++mi) {
            int rb = wm * 32 + mi * 16;
            ldmx4(af[mi], sptr(&As[s][rb + a_row][a_kch]));
        }
        unsigned bf[8][2];
        #pragma unroll
        for (int p = 0; p < 4; ++p) {
            unsigned r[4];
            int n0 = wn * 64 + p * 16;
            ldmx4t(r, sptr(&Bs[s][b_kr][n0 + b_nch]));
            bf[2*p][0] = r[0]; bf[2*p][1] = r[1];
            bf[2*p+1][0] = r[2]; bf[2*p+1][1] = r[3];
        }
        #pragma unroll
        for (int mi = 0; mi < 2; ++mi)
            #pragma unroll
            for (int ni = 0; ni < 8; ++ni)
                mma16816(acc[mi][ni], af[mi], bf[ni]);

        if (kt + 1 < NKT) {
            sts_stage(s ^ 1);                   // writes the buffer NOT being read this iter
            if (kt + 2 < NKT) ldg_stage((kt + 2) * BK);
            __syncthreads();
        }
    }

    // ---- fused epilogue: out[b,row] += sum_j acc(row,j) * t2[b,row,jc+j] ----
    float ps[4] = {0.f, 0.f, 0.f, 0.f};
    #pragma unroll
    for (int mi = 0; mi < 2; ++mi) {
        int r0 = wm * 32 + mi * 16 + gid;
        #pragma unroll
        for (int ni = 0; ni < 8; ++ni) {
            int c = jc + wn * 64 + ni * 8 + 2 * tig;
            float2 u = *(const float2*)(T2g + (size_t)r0 * D2 + c);
            float2 v = *(const float2*)(T2g + (size_t)(r0 + 8) * D2 + c);
            ps[mi * 2 + 0] += acc[mi][ni][0] * u.x + acc[mi][ni][1] * u.y;
            ps[mi * 2 + 1] += acc[mi][ni][2] * v.x + acc[mi][ni][3] * v.y;
        }
    }
    #pragma unroll
    for (int r = 0; r < 4; ++r) {
        ps[r] += __shfl_xor_sync(0xffffffffu, ps[r], 1);
        ps[r] += __shfl_xor_sync(0xffffffffu, ps[r], 2);
    }
    if (tig == 0) {
        #pragma unroll
        for (int mi = 0; mi < 2; ++mi) {
            int r0 = wm * 32 + mi * 16 + gid;
            atomicAdd(&out[b * LSEQ + r0],     ps[mi * 2 + 0]);
            atomicAdd(&out[b * LSEQ + r0 + 8], ps[mi * 2 + 1]);
        }
    }
}

extern "C" void kernel_launch(void* const* d_in, const int* in_sizes, int n_in,
                              void* d_out, int out_size)
{
    (void)in_sizes; (void)n_in; (void)out_size;
    const float* t1  = (const float*)d_in[0];
    const float* t2  = (const float*)d_in[1];
    const int*   idx = (const int*)  d_in[2];
    const float* W   = (const float*)d_in[3];
    float* out = (float*)d_out;

    const int n = BATCH * LSEQ;
    zero_out_kernel<<<(n + 255) / 256, 256>>>(out, n);

    dim3 grid(D2 / BN, BATCH);
    pdot_h_kernel<<<grid, 256>>>(t1, t2, idx, W, out);
}

// round 9
// speedup vs baseline: 1.7683x; 1.7683x over previous
#include <cuda_runtime.h>
#include <cuda_fp16.h>
#include <cstdint>

// Problem constants
#define BATCH 256
#define LSEQ  128
#define E_EXP 64
#define D1    512
#define D2    512

// Tiling
#define BM 128
#define BN 128
#define BK 16              // k elements per stage
#define NKT (D1/BK)        // 32 stages
#define NSTAGE 4
#define ASTR 24            // halves per A smem row (16 + 8 pad)
#define BSTR 136           // halves per B smem row (128 + 8 pad)

// fp16 scratch (static device arrays -- no allocation)
__device__ __half g_t1h[BATCH * LSEQ * D1];   // 32 MB
__device__ __half g_wh[E_EXP * D1 * D2];      // 32 MB

__device__ __forceinline__ unsigned sptr(const void* p) {
    unsigned a;
    asm("{ .reg .u64 t; cvta.to.shared.u64 t, %1; cvt.u32.u64 %0, t; }" : "=r"(a) : "l"(p));
    return a;
}
__device__ __forceinline__ void cpasync16(unsigned dst_s, const void* src) {
    asm volatile("cp.async.cg.shared.global [%0], [%1], 16;\n" :: "r"(dst_s), "l"(src));
}
__device__ __forceinline__ void cp_commit() {
    asm volatile("cp.async.commit_group;\n" ::: "memory");
}
template <int N>
__device__ __forceinline__ void cp_wait() {
    asm volatile("cp.async.wait_group %0;\n" :: "n"(N) : "memory");
}
__device__ __forceinline__ void ldmx4(unsigned* r, unsigned a) {
    asm volatile("ldmatrix.sync.aligned.m8n8.x4.shared.b16 {%0,%1,%2,%3}, [%4];"
                 : "=r"(r[0]), "=r"(r[1]), "=r"(r[2]), "=r"(r[3]) : "r"(a));
}
__device__ __forceinline__ void ldmx4t(unsigned* r, unsigned a) {
    asm volatile("ldmatrix.sync.aligned.m8n8.x4.trans.shared.b16 {%0,%1,%2,%3}, [%4];"
                 : "=r"(r[0]), "=r"(r[1]), "=r"(r[2]), "=r"(r[3]) : "r"(a));
}
__device__ __forceinline__ void mma16816(float* c, const unsigned* a, const unsigned* b) {
    asm volatile(
        "mma.sync.aligned.m16n8k16.row.col.f32.f16.f16.f32 "
        "{%0,%1,%2,%3}, {%4,%5,%6,%7}, {%8,%9}, {%0,%1,%2,%3};"
        : "+f"(c[0]), "+f"(c[1]), "+f"(c[2]), "+f"(c[3])
        : "r"(a[0]), "r"(a[1]), "r"(a[2]), "r"(a[3]), "r"(b[0]), "r"(b[1]));
}

__global__ void zero_out_kernel(float* o, int n) {
    int i = blockIdx.x * blockDim.x + threadIdx.x;
    if (i < n) o[i] = 0.0f;
}

__global__ void cvt_f2h_kernel(const float* __restrict__ src, __half* __restrict__ dst, int n) {
    int i = (blockIdx.x * blockDim.x + threadIdx.x) * 8;
    if (i < n) {
        float4 f0 = *(const float4*)(src + i);
        float4 f1 = *(const float4*)(src + i + 4);
        __half2 h[4];
        h[0] = __floats2half2_rn(f0.x, f0.y);
        h[1] = __floats2half2_rn(f0.z, f0.w);
        h[2] = __floats2half2_rn(f1.x, f1.y);
        h[3] = __floats2half2_rn(f1.z, f1.w);
        *(uint4*)(dst + i) = *(uint4*)h;
    }
}

// grid: (D2/BN = 4, BATCH = 256), block: 256 threads (8 warps, 4m x 2n warp grid)
__global__ __launch_bounds__(256, 2) void pdot_h2_kernel(
    const float* __restrict__ t2,
    const int*   __restrict__ pidx,
    float*       __restrict__ out)
{
    __shared__ __align__(16) __half As[NSTAGE][BM][ASTR];
    __shared__ __align__(16) __half Bs[NSTAGE][BK][BSTR];

    const int b  = blockIdx.y;
    const int jc = blockIdx.x * BN;
    const int e  = pidx[b];

    const __half* Agh = g_t1h + (size_t)b * LSEQ * D1;
    const __half* Wgh = g_wh  + (size_t)e * D1 * D2;
    const float*  T2g = t2    + (size_t)b * LSEQ * D2;

    const int tid  = threadIdx.x;
    const int lane = tid & 31;
    const int warp = tid >> 5;
    const int gid  = lane >> 2;
    const int tig  = lane & 3;
    const int wm   = warp >> 1;     // 0..3 -> 32-row strip
    const int wn   = warp & 1;      // 0..1 -> 64-col strip

    // loader indexing: 2 cp.async per thread per stage
    const int al = tid >> 1;              // A row 0..127
    const int ac = (tid & 1) * 8;         // A col chunk (8 halves)
    const int bk = tid >> 4;              // B k-row 0..15
    const int bc = (tid & 15) * 8;        // B n chunk (8 halves)

    auto load_stage = [&](int s, int k0) {
        cpasync16(sptr(&As[s][al][ac]), Agh + (size_t)al * D1 + k0 + ac);
        cpasync16(sptr(&Bs[s][bk][bc]), Wgh + (size_t)(k0 + bk) * D2 + jc + bc);
        cp_commit();
    };

    // per-thread ldmatrix offsets (proven mapping from R5)
    const int a_row = ((lane >> 3) & 1) * 8 + (lane & 7);
    const int a_kch = (lane >> 4) * 8;
    const int b_kr  = ((lane >> 3) & 1) * 8 + (lane & 7);
    const int b_nch = (lane >> 4) * 8;

    float acc[2][8][4];
    #pragma unroll
    for (int mi = 0; mi < 2; ++mi)
        #pragma unroll
        for (int ni = 0; ni < 8; ++ni)
            #pragma unroll
            for (int r = 0; r < 4; ++r) acc[mi][ni][r] = 0.0f;

    // prologue: 3 stages in flight
    load_stage(0, 0);
    load_stage(1, BK);
    load_stage(2, 2 * BK);

    for (int kt = 0; kt < NKT; ++kt) {
        const int rem = (NKT - 1) - kt;
        if      (rem >= 2) cp_wait<2>();
        else if (rem == 1) cp_wait<1>();
        else               cp_wait<0>();
        __syncthreads();

        // issue next stage's loads before computing (overwrites buffer read at kt-1,
        // which all warps finished before this barrier)
        if (kt + 3 < NKT) load_stage((kt + 3) & 3, (kt + 3) * BK);

        const int s = kt & 3;
        unsigned af[2][4];
        #pragma unroll
        for (int mi = 0; mi < 2; ++mi) {
            int rb = wm * 32 + mi * 16;
            ldmx4(af[mi], sptr(&As[s][rb + a_row][a_kch]));
        }
        unsigned bf[8][2];
        #pragma unroll
        for (int p = 0; p < 4; ++p) {
            unsigned r[4];
            int n0 = wn * 64 + p * 16;
            ldmx4t(r, sptr(&Bs[s][b_kr][n0 + b_nch]));
            bf[2*p][0] = r[0]; bf[2*p][1] = r[1];
            bf[2*p+1][0] = r[2]; bf[2*p+1][1] = r[3];
        }
        #pragma unroll
        for (int mi = 0; mi < 2; ++mi)
            #pragma unroll
            for (int ni = 0; ni < 8; ++ni)
                mma16816(acc[mi][ni], af[mi], bf[ni]);
    }

    // fused epilogue: out[b,row] += sum_j acc(row,j) * t2[b,row,jc+j]
    float ps[4] = {0.f, 0.f, 0.f, 0.f};
    #pragma unroll
    for (int mi = 0; mi < 2; ++mi) {
        int r0 = wm * 32 + mi * 16 + gid;
        #pragma unroll
        for (int ni = 0; ni < 8; ++ni) {
            int c = jc + wn * 64 + ni * 8 + 2 * tig;
            float2 u = *(const float2*)(T2g + (size_t)r0 * D2 + c);
            float2 v = *(const float2*)(T2g + (size_t)(r0 + 8) * D2 + c);
            ps[mi * 2 + 0] += acc[mi][ni][0] * u.x + acc[mi][ni][1] * u.y;
            ps[mi * 2 + 1] += acc[mi][ni][2] * v.x + acc[mi][ni][3] * v.y;
        }
    }
    #pragma unroll
    for (int r = 0; r < 4; ++r) {
        ps[r] += __shfl_xor_sync(0xffffffffu, ps[r], 1);
        ps[r] += __shfl_xor_sync(0xffffffffu, ps[r], 2);
    }
    if (tig == 0) {
        #pragma unroll
        for (int mi = 0; mi < 2; ++mi) {
            int r0 = wm * 32 + mi * 16 + gid;
            atomicAdd(&out[b * LSEQ + r0],     ps[mi * 2 + 0]);
            atomicAdd(&out[b * LSEQ + r0 + 8], ps[mi * 2 + 1]);
        }
    }
}

extern "C" void kernel_launch(void* const* d_in, const int* in_sizes, int n_in,
                              void* d_out, int out_size)
{
    (void)in_sizes; (void)n_in; (void)out_size;
    const float* t1  = (const float*)d_in[0];
    const float* t2  = (const float*)d_in[1];
    const int*   idx = (const int*)  d_in[2];
    const float* W   = (const float*)d_in[3];
    float* out = (float*)d_out;

    // resolve scratch symbol addresses (host-side, capture-safe)
    __half* t1h = nullptr;  __half* wh = nullptr;
    cudaGetSymbolAddress((void**)&t1h, g_t1h);
    cudaGetSymbolAddress((void**)&wh,  g_wh);

    const int n_t1 = BATCH * LSEQ * D1;   // 16,777,216
    const int n_w  = E_EXP * D1 * D2;     // 16,777,216
    cvt_f2h_kernel<<<n_t1 / 8 / 256, 256>>>(t1, t1h, n_t1);
    cvt_f2h_kernel<<<n_w  / 8 / 256, 256>>>(W,  wh,  n_w);

    const int n = BATCH * LSEQ;
    zero_out_kernel<<<(n + 255) / 256, 256>>>(out, n);

    dim3 grid(D2 / BN, BATCH);
    pdot_h2_kernel<<<grid, 256>>>(t2, idx, out);
}